// round 14
// baseline (speedup 1.0000x reference)
#include <cuda_runtime.h>
#include <cuda_fp16.h>
#include <cstdint>
#include <cstddef>

constexpr int Bc  = 4;
constexpr int Sc  = 2048;
constexpr int Dc  = 1024;
constexpr int Hc  = 16;
constexpr int DKc = 64;
constexpr long long BSD  = (long long)Bc * Sc * Dc;       // 8,388,608
constexpr long long BHSS = (long long)Bc * Hc * Sc * Sc;  // 268,435,456
constexpr int ROWS_TOT = Bc * Hc * Sc;                    // 131072
constexpr int NTILES   = Sc / 128;                        // 16

#define ALPHA_LOG2 0.18033688011112042592f   // 0.125 * log2(e)

// Scratch (allocation-free, graph-safe)
__device__ __half g_xq16[Bc * Sc * Dc];
__device__ __half g_xk16[Bc * Sc * Dc];
__device__ __half g_xv16[Bc * Sc * Dc];
__device__ __half g_wq16[Dc * Dc];
__device__ __half g_wk16[Dc * Dc];
__device__ __half g_wv16[Dc * Dc];
__device__ __half g_q16[Bc * Sc * Dc];
__device__ __half g_k16[Bc * Sc * Dc];
__device__ __half g_v16[Bc * Sc * Dc];
__device__ float  g_ctx[Bc * Sc * Dc];
__device__ float  g_attn[(size_t)Bc * Hc * Sc * Sc];
__device__ float2 g_stats[(size_t)ROWS_TOT * NTILES];
__device__ float2 g_rowstats[ROWS_TOT];

// ---------------------------------------------------------------------------
// helpers
// ---------------------------------------------------------------------------
__device__ __forceinline__ uint32_t f2tf(float x) {
    uint32_t u;
    asm("cvt.rna.tf32.f32 %0, %1;" : "=r"(u) : "f"(x));
    return u;
}

__device__ __forceinline__ void mma_tf32(float* c, const uint32_t* a, const uint32_t* b) {
    asm volatile(
        "mma.sync.aligned.m16n8k8.row.col.f32.tf32.tf32.f32 "
        "{%0,%1,%2,%3},{%4,%5,%6,%7},{%8,%9},{%0,%1,%2,%3};"
        : "+f"(c[0]), "+f"(c[1]), "+f"(c[2]), "+f"(c[3])
        : "r"(a[0]), "r"(a[1]), "r"(a[2]), "r"(a[3]), "r"(b[0]), "r"(b[1]));
}

__device__ __forceinline__ void mma_f16(float* c, const uint32_t* a, const uint32_t* b) {
    asm volatile(
        "mma.sync.aligned.m16n8k16.row.col.f32.f16.f16.f32 "
        "{%0,%1,%2,%3},{%4,%5,%6,%7},{%8,%9},{%0,%1,%2,%3};"
        : "+f"(c[0]), "+f"(c[1]), "+f"(c[2]), "+f"(c[3])
        : "r"(a[0]), "r"(a[1]), "r"(a[2]), "r"(a[3]), "r"(b[0]), "r"(b[1]));
}

__device__ __forceinline__ void ldm_x4(uint32_t* r, const __half* p) {
    uint32_t a = (uint32_t)__cvta_generic_to_shared(p);
    asm volatile("ldmatrix.sync.aligned.m8n8.x4.shared.b16 {%0,%1,%2,%3}, [%4];"
        : "=r"(r[0]), "=r"(r[1]), "=r"(r[2]), "=r"(r[3]) : "r"(a));
}
__device__ __forceinline__ void ldm_x4_t(uint32_t* r, const __half* p) {
    uint32_t a = (uint32_t)__cvta_generic_to_shared(p);
    asm volatile("ldmatrix.sync.aligned.m8n8.x4.trans.shared.b16 {%0,%1,%2,%3}, [%4];"
        : "=r"(r[0]), "=r"(r[1]), "=r"(r[2]), "=r"(r[3]) : "r"(a));
}

__device__ __forceinline__ void cpa16(void* dst, const void* src) {
    uint32_t d = (uint32_t)__cvta_generic_to_shared(dst);
    asm volatile("cp.async.cg.shared.global [%0], [%1], 16;" :: "r"(d), "l"(src));
}
__device__ __forceinline__ void cpa_commit() { asm volatile("cp.async.commit_group;"); }
template<int N> __device__ __forceinline__ void cpa_wait() {
    asm volatile("cp.async.wait_group %0;" :: "n"(N));
}

// ---------------------------------------------------------------------------
// fp32 -> fp16 converter
// ---------------------------------------------------------------------------
__global__ __launch_bounds__(256) void cvt_f32_f16(
    const float* __restrict__ in, __half* __restrict__ out, int n4)
{
    int i = blockIdx.x * 256 + threadIdx.x;
    if (i < n4) {
        float4 v = ((const float4*)in)[i];
        __half2 h0 = __floats2half2_rn(v.x, v.y);
        __half2 h1 = __floats2half2_rn(v.z, v.w);
        uint2 u;
        u.x = *(uint32_t*)&h0;
        u.y = *(uint32_t*)&h1;
        ((uint2*)out)[i] = u;
    }
}

// ---------------------------------------------------------------------------
// fp16 NT projection: C16 = A16 @ B16^T + bias (fp16 out). BM=BN=128, BK=32.
// ---------------------------------------------------------------------------
__global__ __launch_bounds__(256) void proj16_kernel(
    const __half* __restrict__ A, const __half* __restrict__ B,
    const float* __restrict__ bias, __half* __restrict__ C,
    int M, int N, int K)
{
    __shared__ __align__(16) __half As[2][128][40];
    __shared__ __align__(16) __half Bs[2][128][40];

    const int tid  = threadIdx.x;
    const int warp = tid >> 5;
    const int lane = tid & 31;
    const int g    = lane >> 2;
    const int tg   = lane & 3;
    const int wm   = warp & 1;
    const int wn   = warp >> 1;
    const int m0   = blockIdx.y * 128;
    const int n0   = blockIdx.x * 128;

    const __half* Ap = A + (size_t)m0 * K;
    const __half* Bp = B + (size_t)n0 * K;

    const int a_r = lane & 15;
    const int a_c = (lane & 16) >> 1;
    const int b_r = ((lane & 16) >> 1) + (lane & 7);
    const int b_c = lane & 8;

    auto stage = [&](int k0, int s) {
#pragma unroll
        for (int i = 0; i < 2; i++) {
            int c = tid + i * 256;
            int row = c >> 2, off = (c & 3) * 8;
            cpa16(&As[s][row][off], Ap + (size_t)row * K + k0 + off);
        }
#pragma unroll
        for (int i = 0; i < 2; i++) {
            int c = tid + i * 256;
            int row = c >> 2, off = (c & 3) * 8;
            cpa16(&Bs[s][row][off], Bp + (size_t)row * K + k0 + off);
        }
    };

    float acc[4][4][4] = {};

    stage(0, 0);
    cpa_commit();

    const int NIT = K / 32;
    for (int it = 0; it < NIT; it++) {
        const int cur = it & 1;
        if (it + 1 < NIT) {
            stage((it + 1) * 32, cur ^ 1);
            cpa_commit();
            cpa_wait<1>();
        } else {
            cpa_wait<0>();
        }
        __syncthreads();

#pragma unroll
        for (int ks = 0; ks < 2; ks++) {
            uint32_t af[4][4], bf[2][4];
#pragma unroll
            for (int i = 0; i < 4; i++)
                ldm_x4(af[i], &As[cur][wm * 64 + i * 16 + a_r][ks * 16 + a_c]);
#pragma unroll
            for (int j2 = 0; j2 < 2; j2++)
                ldm_x4(bf[j2], &Bs[cur][wn * 32 + j2 * 16 + b_r][ks * 16 + b_c]);
#pragma unroll
            for (int i = 0; i < 4; i++)
#pragma unroll
                for (int j = 0; j < 4; j++)
                    mma_f16(acc[i][j], af[i], &bf[j >> 1][(j & 1) * 2]);
        }
        __syncthreads();
    }

#pragma unroll
    for (int i = 0; i < 4; i++) {
#pragma unroll
        for (int j = 0; j < 4; j++) {
            int row = m0 + wm * 64 + i * 16 + g;
            int col = n0 + wn * 32 + j * 8 + 2 * tg;
            float b0 = bias[col], b1 = bias[col + 1];
            *(__half2*)(C + (size_t)row * N + col) =
                __floats2half2_rn(acc[i][j][0] + b0, acc[i][j][1] + b1);
            *(__half2*)(C + (size_t)(row + 8) * N + col) =
                __floats2half2_rn(acc[i][j][2] + b0, acc[i][j][3] + b1);
        }
    }
}

// ---------------------------------------------------------------------------
// Scores + split-softmax stats: per (b,h) T = (q16 @ k16^T)*ALPHA_LOG2 (fp32)
// plus per-tile per-row (max, sum 2^(t-max)).
// ---------------------------------------------------------------------------
__global__ __launch_bounds__(256) void scores16_stats_kernel(
    float* __restrict__ attn, float2* __restrict__ stats,
    const __half* __restrict__ q16, const __half* __restrict__ k16)
{
    __shared__ __align__(16) __half Aq[128][72];
    __shared__ __align__(16) __half Bk[128][72];
    __shared__ float red[128][5];
    __shared__ float rowM[128];

    const int z  = blockIdx.z;
    const int zb = z >> 4;
    const int zh = z & 15;
    const int m0 = blockIdx.y * 128;
    const int n0 = blockIdx.x * 128;
    const __half* Ap = q16 + ((size_t)zb * Sc + m0) * Dc + zh * DKc;
    const __half* Bp = k16 + ((size_t)zb * Sc + n0) * Dc + zh * DKc;
    float* Cb = attn + (size_t)z * Sc * Sc;

    const int tid  = threadIdx.x;
    const int warp = tid >> 5;
    const int lane = tid & 31;
    const int g    = lane >> 2;
    const int tg   = lane & 3;
    const int wm   = warp & 1;
    const int wn   = warp >> 1;

    const int a_r = lane & 15;
    const int a_c = (lane & 16) >> 1;
    const int b_r = ((lane & 16) >> 1) + (lane & 7);
    const int b_c = lane & 8;

#pragma unroll
    for (int i = 0; i < 4; i++) {
        int c = tid + i * 256;
        int row = c >> 3, off = (c & 7) * 8;
        cpa16(&Aq[row][off], Ap + (size_t)row * Dc + off);
    }
#pragma unroll
    for (int i = 0; i < 4; i++) {
        int c = tid + i * 256;
        int row = c >> 3, off = (c & 7) * 8;
        cpa16(&Bk[row][off], Bp + (size_t)row * Dc + off);
    }
    cpa_commit();
    cpa_wait<0>();
    __syncthreads();

    float acc[4][4][4] = {};

#pragma unroll
    for (int ks = 0; ks < 4; ks++) {
        uint32_t af[4][4], bf[2][4];
#pragma unroll
        for (int i = 0; i < 4; i++)
            ldm_x4(af[i], &Aq[wm * 64 + i * 16 + a_r][ks * 16 + a_c]);
#pragma unroll
        for (int j2 = 0; j2 < 2; j2++)
            ldm_x4(bf[j2], &Bk[wn * 32 + j2 * 16 + b_r][ks * 16 + b_c]);
#pragma unroll
        for (int i = 0; i < 4; i++)
#pragma unroll
            for (int j = 0; j < 4; j++)
                mma_f16(acc[i][j], af[i], &bf[j >> 1][(j & 1) * 2]);
    }

    // base-2 logits
#pragma unroll
    for (int i = 0; i < 4; i++)
#pragma unroll
        for (int j = 0; j < 4; j++)
#pragma unroll
            for (int c = 0; c < 4; c++)
                acc[i][j][c] *= ALPHA_LOG2;

    // write t
#pragma unroll
    for (int i = 0; i < 4; i++) {
#pragma unroll
        for (int j = 0; j < 4; j++) {
            int row = m0 + wm * 64 + i * 16 + g;
            int col = n0 + wn * 32 + j * 8 + 2 * tg;
            *(float2*)(Cb + (size_t)row * Sc + col) =
                make_float2(acc[i][j][0], acc[i][j][1]);
            *(float2*)(Cb + (size_t)(row + 8) * Sc + col) =
                make_float2(acc[i][j][2], acc[i][j][3]);
        }
    }

    // per-tile row stats
    float tmax[4][2];
#pragma unroll
    for (int i = 0; i < 4; i++)
#pragma unroll
        for (int hf = 0; hf < 2; hf++) {
            float mv = -1e30f;
#pragma unroll
            for (int j = 0; j < 4; j++)
                mv = fmaxf(mv, fmaxf(acc[i][j][hf * 2], acc[i][j][hf * 2 + 1]));
            mv = fmaxf(mv, __shfl_xor_sync(0xffffffffu, mv, 1));
            mv = fmaxf(mv, __shfl_xor_sync(0xffffffffu, mv, 2));
            tmax[i][hf] = mv;
        }
    if (tg == 0) {
#pragma unroll
        for (int i = 0; i < 4; i++)
#pragma unroll
            for (int hf = 0; hf < 2; hf++)
                red[wm * 64 + i * 16 + g + hf * 8][wn] = tmax[i][hf];
    }
    __syncthreads();
    if (tid < 128) {
        float m4 = red[tid][0];
#pragma unroll
        for (int w = 1; w < 4; w++) m4 = fmaxf(m4, red[tid][w]);
        rowM[tid] = m4;
    }
    __syncthreads();
#pragma unroll
    for (int i = 0; i < 4; i++)
#pragma unroll
        for (int hf = 0; hf < 2; hf++) {
            int r = wm * 64 + i * 16 + g + hf * 8;
            float M = rowM[r];
            float sv = 0.f;
#pragma unroll
            for (int j = 0; j < 4; j++)
                sv += exp2f(acc[i][j][hf * 2] - M) + exp2f(acc[i][j][hf * 2 + 1] - M);
            sv += __shfl_xor_sync(0xffffffffu, sv, 1);
            sv += __shfl_xor_sync(0xffffffffu, sv, 2);
            if (tg == 0) red[r][wn] = sv;
        }
    __syncthreads();
    if (tid < 128) {
        float s4 = red[tid][0];
#pragma unroll
        for (int w = 1; w < 4; w++) s4 += red[tid][w];
        stats[((size_t)z * Sc + m0 + tid) * NTILES + blockIdx.x] =
            make_float2(rowM[tid], s4);
    }
}

// ---------------------------------------------------------------------------
// Combine per-tile stats -> per-row (M, 1/S)
// ---------------------------------------------------------------------------
__global__ __launch_bounds__(256) void combine_kernel(
    const float2* __restrict__ stats, float2* __restrict__ rowstats)
{
    int r = blockIdx.x * 256 + threadIdx.x;
    float2 st[NTILES];
    float M = -1e30f;
#pragma unroll
    for (int t = 0; t < NTILES; t++) {
        st[t] = stats[(size_t)r * NTILES + t];
        M = fmaxf(M, st[t].x);
    }
    float S = 0.f;
#pragma unroll
    for (int t = 0; t < NTILES; t++)
        S += st[t].y * exp2f(st[t].x - M);
    rowstats[r] = make_float2(M, 1.0f / S);
}

// ---------------------------------------------------------------------------
// Fused normalize + ctx GEMM (fp32 ctx out).
// Stages t (fp32) + V (fp16) via cp.async; p = 2^(t-M)*invS -> attn (final),
// fp16 copy into Ah, MMA vs V, fp32 accum -> g_ctx.
// Dyn smem: At[2][128][68] f32 | Bv[2][64][72] h | Ah[128][72] h = 106496 B
// ---------------------------------------------------------------------------
__global__ __launch_bounds__(256) void ctx_fused_kernel(
    float* __restrict__ attn, const float2* __restrict__ rowstats,
    const __half* __restrict__ v16, float* __restrict__ ctx)
{
    extern __shared__ __align__(16) char smraw[];
    float*  At = (float*)smraw;                          // [2][128][68]
    __half* Bv = (__half*)(smraw + 2 * 128 * 68 * 4);    // [2][64][72]
    __half* Ah = Bv + 2 * 64 * 72;                       // [128][72]

    __shared__ float Ms[128], Is[128];

    const int z  = blockIdx.y;
    const int zb = z >> 4;
    const int zh = z & 15;
    const int m0 = blockIdx.x * 128;

    float* Ap = attn + ((size_t)z * Sc + m0) * Sc;
    const __half* Vp = v16 + (size_t)zb * Sc * Dc + zh * DKc;
    float* C = ctx + ((size_t)zb * Sc + m0) * Dc + zh * DKc;

    const int tid  = threadIdx.x;
    const int warp = tid >> 5;
    const int lane = tid & 31;
    const int g    = lane >> 2;
    const int tg   = lane & 3;
    const int wm   = warp & 3;
    const int wn   = warp >> 2;

    const int a_r  = lane & 15;
    const int a_c  = (lane & 16) >> 1;
    const int bt_r = (lane & 8) + (lane & 7);
    const int bt_c = (lane & 16) >> 1;

    if (tid < 128) {
        float2 st = rowstats[(size_t)z * Sc + m0 + tid];
        Ms[tid] = st.x;
        Is[tid] = st.y;
    }

    auto stage = [&](int k0, int s) {
        float* Ad = At + s * 128 * 68;
#pragma unroll
        for (int i = 0; i < 8; i++) {
            int c = tid + i * 256;
            int row = c >> 4, off = (c & 15) * 4;
            cpa16(Ad + row * 68 + off, Ap + (size_t)row * Sc + k0 + off);
        }
#pragma unroll
        for (int i = 0; i < 2; i++) {
            int c = tid + i * 256;
            int kr = c >> 3, off = (c & 7) * 8;
            cpa16(Bv + (s * 64 + kr) * 72 + off, Vp + (size_t)(k0 + kr) * Dc + off);
        }
    };

    float acc[2][4][4] = {};

    stage(0, 0);
    cpa_commit();

    const int t_row  = tid >> 1;
    const int t_base = (tid & 1) * 32;

    const int NIT = Sc / 64;   // 32
    for (int it = 0; it < NIT; it++) {
        const int cur = it & 1;
        const int k0 = it * 64;
        if (it + 1 < NIT) {
            stage(k0 + 64, cur ^ 1);
            cpa_commit();
            cpa_wait<1>();
        } else {
            cpa_wait<0>();
        }
        __syncthreads();   // At[cur]/Bv[cur] ready; prior Ah reads done; Ms/Is ready

        // transform: t -> p (gmem, final attn) + fp16 (Ah)
        {
            const float* Ats = At + cur * 128 * 68 + t_row * 68 + t_base;
            float* gp = Ap + (size_t)t_row * Sc + k0 + t_base;
            __half* ah = Ah + t_row * 72 + t_base;
            const float M = Ms[t_row], I = Is[t_row];
#pragma unroll
            for (int c = 0; c < 8; c++) {
                float4 t4 = *(const float4*)(Ats + c * 4);
                float4 p4;
                p4.x = exp2f(t4.x - M) * I;
                p4.y = exp2f(t4.y - M) * I;
                p4.z = exp2f(t4.z - M) * I;
                p4.w = exp2f(t4.w - M) * I;
                *(float4*)(gp + c * 4) = p4;
                __half2 h01 = __floats2half2_rn(p4.x, p4.y);
                __half2 h23 = __floats2half2_rn(p4.z, p4.w);
                uint2 u;
                u.x = *(uint32_t*)&h01;
                u.y = *(uint32_t*)&h23;
                *(uint2*)(ah + c * 4) = u;
            }
        }
        __syncthreads();   // Ah ready

#pragma unroll
        for (int ks = 0; ks < 4; ks++) {
            uint32_t af[2][4], bf[2][4];
#pragma unroll
            for (int i = 0; i < 2; i++)
                ldm_x4(af[i], &Ah[(wm * 32 + i * 16 + a_r) * 72 + ks * 16 + a_c]);
#pragma unroll
            for (int j2 = 0; j2 < 2; j2++)
                ldm_x4_t(bf[j2], &Bv[(cur * 64 + ks * 16 + bt_r) * 72 + wn * 32 + j2 * 16 + bt_c]);
#pragma unroll
            for (int i = 0; i < 2; i++)
#pragma unroll
                for (int j = 0; j < 4; j++)
                    mma_f16(acc[i][j], af[i], &bf[j >> 1][(j & 1) * 2]);
        }
    }

#pragma unroll
    for (int i = 0; i < 2; i++) {
#pragma unroll
        for (int j = 0; j < 4; j++) {
            int row = wm * 32 + i * 16 + g;
            int col = wn * 32 + j * 8 + 2 * tg;
            *(float2*)(C + (size_t)row * Dc + col) =
                make_float2(acc[i][j][0], acc[i][j][1]);
            *(float2*)(C + (size_t)(row + 8) * Dc + col) =
                make_float2(acc[i][j][2], acc[i][j][3]);
        }
    }
}

// ---------------------------------------------------------------------------
// tf32 NT GEMM (round-11, proven) for the fp32 output projection.
// ---------------------------------------------------------------------------
__global__ __launch_bounds__(256) void proj_nt_kernel(
    const float* __restrict__ A, const float* __restrict__ B,
    float* __restrict__ C, const float* __restrict__ bias,
    int M, int N, int K)
{
    constexpr int BK = 16, ST = 20;

    __shared__ float As[2][128][ST];
    __shared__ float Bs[2][128][ST];

    const int tid  = threadIdx.x;
    const int warp = tid >> 5;
    const int lane = tid & 31;
    const int g    = lane >> 2;
    const int tg   = lane & 3;
    const int wm   = warp & 1;
    const int wn   = warp >> 1;
    const int m0   = blockIdx.y * 128;
    const int n0   = blockIdx.x * 128;

    const float* Ap = A + (size_t)m0 * K;
    const float* Bp = B + (size_t)n0 * K;

    const int lrow = tid >> 2;
    const int lkof = (tid & 3) * 4;

    auto stage = [&](int k0, int s) {
#pragma unroll
        for (int i = 0; i < 2; i++) {
            int row = lrow + i * 64;
            cpa16(&As[s][row][lkof], Ap + (size_t)row * K + k0 + lkof);
        }
#pragma unroll
        for (int i = 0; i < 2; i++) {
            int row = lrow + i * 64;
            cpa16(&Bs[s][row][lkof], Bp + (size_t)row * K + k0 + lkof);
        }
    };

    float acc[4][4][4] = {};

    stage(0, 0);
    cpa_commit();

    const int NIT = K / BK;
    for (int it = 0; it < NIT; it++) {
        const int cur = it & 1;
        if (it + 1 < NIT) {
            stage((it + 1) * BK, cur ^ 1);
            cpa_commit();
            cpa_wait<1>();
        } else {
            cpa_wait<0>();
        }
        __syncthreads();

#pragma unroll
        for (int ks = 0; ks < 2; ks++) {
            const int kk = ks * 8 + tg;
            uint32_t af[4][4], bf[4][2];
#pragma unroll
            for (int i = 0; i < 4; i++) {
                int m = wm * 64 + i * 16 + g;
                af[i][0] = f2tf(As[cur][m    ][kk]);
                af[i][1] = f2tf(As[cur][m + 8][kk]);
                af[i][2] = f2tf(As[cur][m    ][kk + 4]);
                af[i][3] = f2tf(As[cur][m + 8][kk + 4]);
            }
#pragma unroll
            for (int j = 0; j < 4; j++) {
                int n = wn * 32 + j * 8 + g;
                bf[j][0] = f2tf(Bs[cur][n][kk]);
                bf[j][1] = f2tf(Bs[cur][n][kk + 4]);
            }
#pragma unroll
            for (int i = 0; i < 4; i++)
#pragma unroll
                for (int j = 0; j < 4; j++)
                    mma_tf32(acc[i][j], af[i], bf[j]);
        }
        __syncthreads();
    }

#pragma unroll
    for (int i = 0; i < 4; i++) {
#pragma unroll
        for (int j = 0; j < 4; j++) {
            int row = m0 + wm * 64 + i * 16 + g;
            int col = n0 + wn * 32 + j * 8 + 2 * tg;
            float b0 = bias[col], b1 = bias[col + 1];
            *(float2*)(C + (size_t)row * N + col) =
                make_float2(acc[i][j][0] + b0, acc[i][j][1] + b1);
            *(float2*)(C + (size_t)(row + 8) * N + col) =
                make_float2(acc[i][j][2] + b0, acc[i][j][3] + b1);
        }
    }
}

// ---------------------------------------------------------------------------
// Host launch
// ---------------------------------------------------------------------------
extern "C" void kernel_launch(void* const* d_in, const int* in_sizes, int n_in,
                              void* d_out, int out_size)
{
    const float* Q  = (const float*)d_in[0];
    const float* K  = (const float*)d_in[1];
    const float* V  = (const float*)d_in[2];
    const float* wq = (const float*)d_in[3];
    const float* bq = (const float*)d_in[4];
    const float* wk = (const float*)d_in[5];
    const float* bk = (const float*)d_in[6];
    const float* wv = (const float*)d_in[7];
    const float* bv = (const float*)d_in[8];
    const float* wo = (const float*)d_in[9];
    const float* bo = (const float*)d_in[10];
    float* out = (float*)d_out;

    __half *xq16, *xk16, *xv16, *wq16, *wk16, *wv16, *q16, *k16, *v16;
    float *cp, *attn_scratch;
    float2 *stats, *rowstats;
    cudaGetSymbolAddress((void**)&xq16, g_xq16);
    cudaGetSymbolAddress((void**)&xk16, g_xk16);
    cudaGetSymbolAddress((void**)&xv16, g_xv16);
    cudaGetSymbolAddress((void**)&wq16, g_wq16);
    cudaGetSymbolAddress((void**)&wk16, g_wk16);
    cudaGetSymbolAddress((void**)&wv16, g_wv16);
    cudaGetSymbolAddress((void**)&q16, g_q16);
    cudaGetSymbolAddress((void**)&k16, g_k16);
    cudaGetSymbolAddress((void**)&v16, g_v16);
    cudaGetSymbolAddress((void**)&cp, g_ctx);
    cudaGetSymbolAddress((void**)&attn_scratch, g_attn);
    cudaGetSymbolAddress((void**)&stats, g_stats);
    cudaGetSymbolAddress((void**)&rowstats, g_rowstats);

    float* attn = ((long long)out_size >= BSD + BHSS) ? (out + BSD) : attn_scratch;

    const int CTX_SMEM = 2 * 128 * 68 * 4 + 2 * 64 * 72 * 2 + 128 * 72 * 2;  // 106496
    cudaFuncSetAttribute(ctx_fused_kernel, cudaFuncAttributeMaxDynamicSharedMemorySize, CTX_SMEM);

    const int M = Bc * Sc;  // 8192
    dim3 blk(256);

    // fp16 conversions
    cvt_f32_f16<<<dim3((int)(BSD / 4 / 256)), blk>>>(Q, xq16, (int)(BSD / 4));
    cvt_f32_f16<<<dim3((int)(BSD / 4 / 256)), blk>>>(K, xk16, (int)(BSD / 4));
    cvt_f32_f16<<<dim3((int)(BSD / 4 / 256)), blk>>>(V, xv16, (int)(BSD / 4));
    cvt_f32_f16<<<dim3(Dc * Dc / 4 / 256), blk>>>(wq, wq16, Dc * Dc / 4);
    cvt_f32_f16<<<dim3(Dc * Dc / 4 / 256), blk>>>(wk, wk16, Dc * Dc / 4);
    cvt_f32_f16<<<dim3(Dc * Dc / 4 / 256), blk>>>(wv, wv16, Dc * Dc / 4);

    // Projections (fp16 out)
    dim3 gProj(Dc / 128, M / 128);
    proj16_kernel<<<gProj, blk>>>(xq16, wq16, bq, q16, M, Dc, Dc);
    proj16_kernel<<<gProj, blk>>>(xk16, wk16, bk, k16, M, Dc, Dc);
    proj16_kernel<<<gProj, blk>>>(xv16, wv16, bv, v16, M, Dc, Dc);

    // Scores (base-2 logits fp32) + stats
    dim3 gScore(Sc / 128, Sc / 128, Bc * Hc);
    scores16_stats_kernel<<<gScore, blk>>>(attn, stats, q16, k16);

    // Combine
    combine_kernel<<<dim3(ROWS_TOT / 256), blk>>>(stats, rowstats);

    // Fused normalize (final attn) + ctx (fp32 out)
    dim3 gCtx(Sc / 128, Bc * Hc);
    ctx_fused_kernel<<<gCtx, blk, CTX_SMEM>>>(attn, rowstats, v16, cp);

    // Output projection (tf32, fp32 out)
    proj_nt_kernel<<<gProj, blk>>>(cp, wo, out, bo, M, Dc, Dc);
}

// round 17
// speedup vs baseline: 1.2742x; 1.2742x over previous
#include <cuda_runtime.h>
#include <cuda_fp16.h>
#include <cstdint>
#include <cstddef>

constexpr int Bc  = 4;
constexpr int Sc  = 2048;
constexpr int Dc  = 1024;
constexpr int Hc  = 16;
constexpr int DKc = 64;
constexpr long long BSD  = (long long)Bc * Sc * Dc;       // 8,388,608
constexpr long long BHSS = (long long)Bc * Hc * Sc * Sc;  // 268,435,456

// Scratch (allocation-free, graph-safe)
__device__ __half g_xq16[Bc * Sc * Dc];
__device__ __half g_xk16[Bc * Sc * Dc];
__device__ __half g_xv16[Bc * Sc * Dc];
__device__ __half g_wq16[Dc * Dc];
__device__ __half g_wk16[Dc * Dc];
__device__ __half g_wv16[Dc * Dc];
__device__ __half g_q16[Bc * Sc * Dc];
__device__ __half g_k16[Bc * Sc * Dc];
__device__ __half g_v16[Bc * Sc * Dc];
__device__ __half g_s16[(size_t)Bc * Hc * Sc * Sc];   // raw scores (fp16)
__device__ __half g_p16[(size_t)Bc * Hc * Sc * Sc];   // softmax p (fp16)
__device__ float  g_ctx[Bc * Sc * Dc];
__device__ float  g_attn[(size_t)Bc * Hc * Sc * Sc];  // fallback attn home

// ---------------------------------------------------------------------------
// helpers
// ---------------------------------------------------------------------------
__device__ __forceinline__ uint32_t f2tf(float x) {
    uint32_t u;
    asm("cvt.rna.tf32.f32 %0, %1;" : "=r"(u) : "f"(x));
    return u;
}

__device__ __forceinline__ void mma_tf32(float* c, const uint32_t* a, const uint32_t* b) {
    asm volatile(
        "mma.sync.aligned.m16n8k8.row.col.f32.tf32.tf32.f32 "
        "{%0,%1,%2,%3},{%4,%5,%6,%7},{%8,%9},{%0,%1,%2,%3};"
        : "+f"(c[0]), "+f"(c[1]), "+f"(c[2]), "+f"(c[3])
        : "r"(a[0]), "r"(a[1]), "r"(a[2]), "r"(a[3]), "r"(b[0]), "r"(b[1]));
}

__device__ __forceinline__ void mma_f16(float* c, const uint32_t* a, const uint32_t* b) {
    asm volatile(
        "mma.sync.aligned.m16n8k16.row.col.f32.f16.f16.f32 "
        "{%0,%1,%2,%3},{%4,%5,%6,%7},{%8,%9},{%0,%1,%2,%3};"
        : "+f"(c[0]), "+f"(c[1]), "+f"(c[2]), "+f"(c[3])
        : "r"(a[0]), "r"(a[1]), "r"(a[2]), "r"(a[3]), "r"(b[0]), "r"(b[1]));
}

__device__ __forceinline__ void ldm_x4(uint32_t* r, const __half* p) {
    uint32_t a = (uint32_t)__cvta_generic_to_shared(p);
    asm volatile("ldmatrix.sync.aligned.m8n8.x4.shared.b16 {%0,%1,%2,%3}, [%4];"
        : "=r"(r[0]), "=r"(r[1]), "=r"(r[2]), "=r"(r[3]) : "r"(a));
}
__device__ __forceinline__ void ldm_x4_t(uint32_t* r, const __half* p) {
    uint32_t a = (uint32_t)__cvta_generic_to_shared(p);
    asm volatile("ldmatrix.sync.aligned.m8n8.x4.trans.shared.b16 {%0,%1,%2,%3}, [%4];"
        : "=r"(r[0]), "=r"(r[1]), "=r"(r[2]), "=r"(r[3]) : "r"(a));
}

__device__ __forceinline__ void cpa16(void* dst, const void* src) {
    uint32_t d = (uint32_t)__cvta_generic_to_shared(dst);
    asm volatile("cp.async.cg.shared.global [%0], [%1], 16;" :: "r"(d), "l"(src));
}
__device__ __forceinline__ void cpa_commit() { asm volatile("cp.async.commit_group;"); }
template<int N> __device__ __forceinline__ void cpa_wait() {
    asm volatile("cp.async.wait_group %0;" :: "n"(N));
}

// ---------------------------------------------------------------------------
// fp32 -> fp16 converter
// ---------------------------------------------------------------------------
__global__ __launch_bounds__(256) void cvt_f32_f16(
    const float* __restrict__ in, __half* __restrict__ out, int n4)
{
    int i = blockIdx.x * 256 + threadIdx.x;
    if (i < n4) {
        float4 v = ((const float4*)in)[i];
        __half2 h0 = __floats2half2_rn(v.x, v.y);
        __half2 h1 = __floats2half2_rn(v.z, v.w);
        uint2 u;
        u.x = *(uint32_t*)&h0;
        u.y = *(uint32_t*)&h1;
        ((uint2*)out)[i] = u;
    }
}

// ---------------------------------------------------------------------------
// fp16 NT projection: C16 = A16 @ B16^T + bias (fp16 out). BM=BN=128, BK=32.
// ---------------------------------------------------------------------------
__global__ __launch_bounds__(256) void proj16_kernel(
    const __half* __restrict__ A, const __half* __restrict__ B,
    const float* __restrict__ bias, __half* __restrict__ C,
    int M, int N, int K)
{
    __shared__ __align__(16) __half As[2][128][40];
    __shared__ __align__(16) __half Bs[2][128][40];

    const int tid  = threadIdx.x;
    const int warp = tid >> 5;
    const int lane = tid & 31;
    const int g    = lane >> 2;
    const int tg   = lane & 3;
    const int wm   = warp & 1;
    const int wn   = warp >> 1;
    const int m0   = blockIdx.y * 128;
    const int n0   = blockIdx.x * 128;

    const __half* Ap = A + (size_t)m0 * K;
    const __half* Bp = B + (size_t)n0 * K;

    const int a_r = lane & 15;
    const int a_c = (lane & 16) >> 1;
    const int b_r = ((lane & 16) >> 1) + (lane & 7);
    const int b_c = lane & 8;

    auto stage = [&](int k0, int s) {
#pragma unroll
        for (int i = 0; i < 2; i++) {
            int c = tid + i * 256;
            int row = c >> 2, off = (c & 3) * 8;
            cpa16(&As[s][row][off], Ap + (size_t)row * K + k0 + off);
        }
#pragma unroll
        for (int i = 0; i < 2; i++) {
            int c = tid + i * 256;
            int row = c >> 2, off = (c & 3) * 8;
            cpa16(&Bs[s][row][off], Bp + (size_t)row * K + k0 + off);
        }
    };

    float acc[4][4][4] = {};

    stage(0, 0);
    cpa_commit();

    const int NIT = K / 32;
    for (int it = 0; it < NIT; it++) {
        const int cur = it & 1;
        if (it + 1 < NIT) {
            stage((it + 1) * 32, cur ^ 1);
            cpa_commit();
            cpa_wait<1>();
        } else {
            cpa_wait<0>();
        }
        __syncthreads();

#pragma unroll
        for (int ks = 0; ks < 2; ks++) {
            uint32_t af[4][4], bf[2][4];
#pragma unroll
            for (int i = 0; i < 4; i++)
                ldm_x4(af[i], &As[cur][wm * 64 + i * 16 + a_r][ks * 16 + a_c]);
#pragma unroll
            for (int j2 = 0; j2 < 2; j2++)
                ldm_x4(bf[j2], &Bs[cur][wn * 32 + j2 * 16 + b_r][ks * 16 + b_c]);
#pragma unroll
            for (int i = 0; i < 4; i++)
#pragma unroll
                for (int j = 0; j < 4; j++)
                    mma_f16(acc[i][j], af[i], &bf[j >> 1][(j & 1) * 2]);
        }
        __syncthreads();
    }

#pragma unroll
    for (int i = 0; i < 4; i++) {
#pragma unroll
        for (int j = 0; j < 4; j++) {
            int row = m0 + wm * 64 + i * 16 + g;
            int col = n0 + wn * 32 + j * 8 + 2 * tg;
            float b0 = bias[col], b1 = bias[col + 1];
            *(__half2*)(C + (size_t)row * N + col) =
                __floats2half2_rn(acc[i][j][0] + b0, acc[i][j][1] + b1);
            *(__half2*)(C + (size_t)(row + 8) * N + col) =
                __floats2half2_rn(acc[i][j][2] + b0, acc[i][j][3] + b1);
        }
    }
}

// ---------------------------------------------------------------------------
// Scores: per (b,h) S = (q16 @ k16^T)/8 -> fp16 scores.
// Full K=64 resident, one bulk cp.async, 4 k16 MMA steps, no mid syncs.
// ---------------------------------------------------------------------------
__global__ __launch_bounds__(256) void scores16_kernel(
    __half* __restrict__ s16,
    const __half* __restrict__ q16, const __half* __restrict__ k16)
{
    __shared__ __align__(16) __half Aq[128][72];
    __shared__ __align__(16) __half Bk[128][72];

    const int z  = blockIdx.z;
    const int zb = z >> 4;
    const int zh = z & 15;
    const int m0 = blockIdx.y * 128;
    const int n0 = blockIdx.x * 128;
    const __half* Ap = q16 + ((size_t)zb * Sc + m0) * Dc + zh * DKc;
    const __half* Bp = k16 + ((size_t)zb * Sc + n0) * Dc + zh * DKc;
    __half* Cb = s16 + (size_t)z * Sc * Sc;

    const int tid  = threadIdx.x;
    const int warp = tid >> 5;
    const int lane = tid & 31;
    const int g    = lane >> 2;
    const int tg   = lane & 3;
    const int wm   = warp & 1;
    const int wn   = warp >> 1;

    const int a_r = lane & 15;
    const int a_c = (lane & 16) >> 1;
    const int b_r = ((lane & 16) >> 1) + (lane & 7);
    const int b_c = lane & 8;

#pragma unroll
    for (int i = 0; i < 4; i++) {
        int c = tid + i * 256;
        int row = c >> 3, off = (c & 7) * 8;
        cpa16(&Aq[row][off], Ap + (size_t)row * Dc + off);
    }
#pragma unroll
    for (int i = 0; i < 4; i++) {
        int c = tid + i * 256;
        int row = c >> 3, off = (c & 7) * 8;
        cpa16(&Bk[row][off], Bp + (size_t)row * Dc + off);
    }
    cpa_commit();
    cpa_wait<0>();
    __syncthreads();

    float acc[4][4][4] = {};

#pragma unroll
    for (int ks = 0; ks < 4; ks++) {
        uint32_t af[4][4], bf[2][4];
#pragma unroll
        for (int i = 0; i < 4; i++)
            ldm_x4(af[i], &Aq[wm * 64 + i * 16 + a_r][ks * 16 + a_c]);
#pragma unroll
        for (int j2 = 0; j2 < 2; j2++)
            ldm_x4(bf[j2], &Bk[wn * 32 + j2 * 16 + b_r][ks * 16 + b_c]);
#pragma unroll
        for (int i = 0; i < 4; i++)
#pragma unroll
            for (int j = 0; j < 4; j++)
                mma_f16(acc[i][j], af[i], &bf[j >> 1][(j & 1) * 2]);
    }

    const float alpha = 0.125f;
#pragma unroll
    for (int i = 0; i < 4; i++) {
#pragma unroll
        for (int j = 0; j < 4; j++) {
            int row = m0 + wm * 64 + i * 16 + g;
            int col = n0 + wn * 32 + j * 8 + 2 * tg;
            *(__half2*)(Cb + (size_t)row * Sc + col) =
                __floats2half2_rn(acc[i][j][0] * alpha, acc[i][j][1] * alpha);
            *(__half2*)(Cb + (size_t)(row + 8) * Sc + col) =
                __floats2half2_rn(acc[i][j][2] * alpha, acc[i][j][3] * alpha);
        }
    }
}

// ---------------------------------------------------------------------------
// Softmax: reads fp16 scores, writes fp32 attn (final output) + fp16 p.
// One 256-thread block per row of 2048.
// ---------------------------------------------------------------------------
__global__ __launch_bounds__(256) void softmax_kernel(
    const __half* __restrict__ s16, float* __restrict__ attn,
    __half* __restrict__ p16)
{
    const __half* sp = s16 + (size_t)blockIdx.x * Sc;
    float* p  = attn + (size_t)blockIdx.x * Sc;
    __half* ph = p16 + (size_t)blockIdx.x * Sc;
    const int tid = threadIdx.x;

    uint2 ua = *(const uint2*)(sp + tid * 4);
    uint2 ub = *(const uint2*)(sp + 1024 + tid * 4);
    __half2 ha0 = *(__half2*)&ua.x, ha1 = *(__half2*)&ua.y;
    __half2 hb0 = *(__half2*)&ub.x, hb1 = *(__half2*)&ub.y;
    float x[8];
    { float2 f = __half22float2(ha0); x[0] = f.x; x[1] = f.y; }
    { float2 f = __half22float2(ha1); x[2] = f.x; x[3] = f.y; }
    { float2 f = __half22float2(hb0); x[4] = f.x; x[5] = f.y; }
    { float2 f = __half22float2(hb1); x[6] = f.x; x[7] = f.y; }

    float m = x[0];
#pragma unroll
    for (int i = 1; i < 8; i++) m = fmaxf(m, x[i]);
#pragma unroll
    for (int o = 16; o > 0; o >>= 1) m = fmaxf(m, __shfl_xor_sync(0xffffffffu, m, o));

    __shared__ float red[8];
    if ((tid & 31) == 0) red[tid >> 5] = m;
    __syncthreads();
    float bm = red[0];
#pragma unroll
    for (int i = 1; i < 8; i++) bm = fmaxf(bm, red[i]);

    float s = 0.f;
#pragma unroll
    for (int i = 0; i < 8; i++) { x[i] = __expf(x[i] - bm); s += x[i]; }
#pragma unroll
    for (int o = 16; o > 0; o >>= 1) s += __shfl_xor_sync(0xffffffffu, s, o);
    __syncthreads();
    if ((tid & 31) == 0) red[tid >> 5] = s;
    __syncthreads();
    float bs = 0.f;
#pragma unroll
    for (int i = 0; i < 8; i++) bs += red[i];

    float inv = 1.0f / bs;
#pragma unroll
    for (int i = 0; i < 8; i++) x[i] *= inv;

    *(float4*)(p + tid * 4)        = make_float4(x[0], x[1], x[2], x[3]);
    *(float4*)(p + 1024 + tid * 4) = make_float4(x[4], x[5], x[6], x[7]);

    __half2 h01 = __floats2half2_rn(x[0], x[1]);
    __half2 h23 = __floats2half2_rn(x[2], x[3]);
    __half2 h45 = __floats2half2_rn(x[4], x[5]);
    __half2 h67 = __floats2half2_rn(x[6], x[7]);
    uint2 u0, u1;
    u0.x = *(uint32_t*)&h01; u0.y = *(uint32_t*)&h23;
    u1.x = *(uint32_t*)&h45; u1.y = *(uint32_t*)&h67;
    *(uint2*)(ph + tid * 4)        = u0;
    *(uint2*)(ph + 1024 + tid * 4) = u1;
}

// ---------------------------------------------------------------------------
// Ctx: per (b,h) ctx = p16 @ v16_head -> fp32. BM=128, BN=64, BK=64,
// 2-stage cp.async, ldmatrix (B transposed load from [k][n]).
// Dynamic smem: A[2][128][72] + B[2][64][72] halves = 55296 B.
// ---------------------------------------------------------------------------
__global__ __launch_bounds__(256) void ctx16_kernel(
    const __half* __restrict__ p16, const __half* __restrict__ v16)
{
    extern __shared__ __half smh[];
    __half (*As)[72] = (__half(*)[72])smh;                    // [2*128][72]
    __half (*Bs)[72] = (__half(*)[72])(smh + 2 * 128 * 72);   // [2*64][72]

    const int z  = blockIdx.y;
    const int zb = z >> 4;
    const int zh = z & 15;
    const int m0 = blockIdx.x * 128;

    const __half* Ap = p16 + ((size_t)z * Sc + m0) * Sc;
    const __half* Vp = v16 + (size_t)zb * Sc * Dc + zh * DKc;
    float* C = g_ctx + ((size_t)zb * Sc + m0) * Dc + zh * DKc;

    const int tid  = threadIdx.x;
    const int warp = tid >> 5;
    const int lane = tid & 31;
    const int g    = lane >> 2;
    const int tg   = lane & 3;
    const int wm   = warp & 3;      // 4 row groups of 32
    const int wn   = warp >> 2;     // 2 col groups of 32

    const int a_r  = lane & 15;
    const int a_c  = (lane & 16) >> 1;
    const int bt_r = (lane & 8) + (lane & 7);
    const int bt_c = (lane & 16) >> 1;

    auto stage = [&](int k0, int s) {
#pragma unroll
        for (int i = 0; i < 4; i++) {
            int c = tid + i * 256;
            int row = c >> 3, off = (c & 7) * 8;
            cpa16(&As[s * 128 + row][off], Ap + (size_t)row * Sc + k0 + off);
        }
#pragma unroll
        for (int i = 0; i < 2; i++) {
            int c = tid + i * 256;
            int kr = c >> 3, off = (c & 7) * 8;
            cpa16(&Bs[s * 64 + kr][off], Vp + (size_t)(k0 + kr) * Dc + off);
        }
    };

    float acc[2][4][4] = {};

    stage(0, 0);
    cpa_commit();

    const int NIT = Sc / 64;   // 32
    for (int it = 0; it < NIT; it++) {
        const int cur = it & 1;
        if (it + 1 < NIT) {
            stage((it + 1) * 64, cur ^ 1);
            cpa_commit();
            cpa_wait<1>();
        } else {
            cpa_wait<0>();
        }
        __syncthreads();

#pragma unroll
        for (int ks = 0; ks < 4; ks++) {
            uint32_t af[2][4], bf[2][4];
#pragma unroll
            for (int i = 0; i < 2; i++)
                ldm_x4(af[i], &As[cur * 128 + wm * 32 + i * 16 + a_r][ks * 16 + a_c]);
#pragma unroll
            for (int j2 = 0; j2 < 2; j2++)
                ldm_x4_t(bf[j2], &Bs[cur * 64 + ks * 16 + bt_r][wn * 32 + j2 * 16 + bt_c]);
#pragma unroll
            for (int i = 0; i < 2; i++)
#pragma unroll
                for (int j = 0; j < 4; j++)
                    mma_f16(acc[i][j], af[i], &bf[j >> 1][(j & 1) * 2]);
        }
        __syncthreads();
    }

#pragma unroll
    for (int i = 0; i < 2; i++) {
#pragma unroll
        for (int j = 0; j < 4; j++) {
            int row = wm * 32 + i * 16 + g;
            int col = wn * 32 + j * 8 + 2 * tg;
            *(float2*)(C + (size_t)row * Dc + col) =
                make_float2(acc[i][j][0], acc[i][j][1]);
            *(float2*)(C + (size_t)(row + 8) * Dc + col) =
                make_float2(acc[i][j][2], acc[i][j][3]);
        }
    }
}

// ---------------------------------------------------------------------------
// tf32 NT GEMM (proven) for the fp32 output projection.
// ---------------------------------------------------------------------------
__global__ __launch_bounds__(256) void proj_nt_kernel(
    const float* __restrict__ A, const float* __restrict__ B,
    float* __restrict__ C, const float* __restrict__ bias,
    int M, int N, int K)
{
    constexpr int BK = 16, ST = 20;

    __shared__ float As[2][128][ST];
    __shared__ float Bs[2][128][ST];

    const int tid  = threadIdx.x;
    const int warp = tid >> 5;
    const int lane = tid & 31;
    const int g    = lane >> 2;
    const int tg   = lane & 3;
    const int wm   = warp & 1;
    const int wn   = warp >> 1;
    const int m0   = blockIdx.y * 128;
    const int n0   = blockIdx.x * 128;

    const float* Ap = A + (size_t)m0 * K;
    const float* Bp = B + (size_t)n0 * K;

    const int lrow = tid >> 2;
    const int lkof = (tid & 3) * 4;

    auto stage = [&](int k0, int s) {
#pragma unroll
        for (int i = 0; i < 2; i++) {
            int row = lrow + i * 64;
            cpa16(&As[s][row][lkof], Ap + (size_t)row * K + k0 + lkof);
        }
#pragma unroll
        for (int i = 0; i < 2; i++) {
            int row = lrow + i * 64;
            cpa16(&Bs[s][row][lkof], Bp + (size_t)row * K + k0 + lkof);
        }
    };

    float acc[4][4][4] = {};

    stage(0, 0);
    cpa_commit();

    const int NIT = K / BK;
    for (int it = 0; it < NIT; it++) {
        const int cur = it & 1;
        if (it + 1 < NIT) {
            stage((it + 1) * BK, cur ^ 1);
            cpa_commit();
            cpa_wait<1>();
        } else {
            cpa_wait<0>();
        }
        __syncthreads();

#pragma unroll
        for (int ks = 0; ks < 2; ks++) {
            const int kk = ks * 8 + tg;
            uint32_t af[4][4], bf[4][2];
#pragma unroll
            for (int i = 0; i < 4; i++) {
                int m = wm * 64 + i * 16 + g;
                af[i][0] = f2tf(As[cur][m    ][kk]);
                af[i][1] = f2tf(As[cur][m + 8][kk]);
                af[i][2] = f2tf(As[cur][m    ][kk + 4]);
                af[i][3] = f2tf(As[cur][m + 8][kk + 4]);
            }
#pragma unroll
            for (int j = 0; j < 4; j++) {
                int n = wn * 32 + j * 8 + g;
                bf[j][0] = f2tf(Bs[cur][n][kk]);
                bf[j][1] = f2tf(Bs[cur][n][kk + 4]);
            }
#pragma unroll
            for (int i = 0; i < 4; i++)
#pragma unroll
                for (int j = 0; j < 4; j++)
                    mma_tf32(acc[i][j], af[i], bf[j]);
        }
        __syncthreads();
    }

#pragma unroll
    for (int i = 0; i < 4; i++) {
#pragma unroll
        for (int j = 0; j < 4; j++) {
            int row = m0 + wm * 64 + i * 16 + g;
            int col = n0 + wn * 32 + j * 8 + 2 * tg;
            float b0 = bias[col], b1 = bias[col + 1];
            *(float2*)(C + (size_t)row * N + col) =
                make_float2(acc[i][j][0] + b0, acc[i][j][1] + b1);
            *(float2*)(C + (size_t)(row + 8) * N + col) =
                make_float2(acc[i][j][2] + b0, acc[i][j][3] + b1);
        }
    }
}

// ---------------------------------------------------------------------------
// Host launch
// ---------------------------------------------------------------------------
extern "C" void kernel_launch(void* const* d_in, const int* in_sizes, int n_in,
                              void* d_out, int out_size)
{
    const float* Q  = (const float*)d_in[0];
    const float* K  = (const float*)d_in[1];
    const float* V  = (const float*)d_in[2];
    const float* wq = (const float*)d_in[3];
    const float* bq = (const float*)d_in[4];
    const float* wk = (const float*)d_in[5];
    const float* bk = (const float*)d_in[6];
    const float* wv = (const float*)d_in[7];
    const float* bv = (const float*)d_in[8];
    const float* wo = (const float*)d_in[9];
    const float* bo = (const float*)d_in[10];
    float* out = (float*)d_out;

    __half *xq16, *xk16, *xv16, *wq16, *wk16, *wv16, *q16, *k16, *v16, *s16, *p16;
    float *cp, *attn_scratch;
    cudaGetSymbolAddress((void**)&xq16, g_xq16);
    cudaGetSymbolAddress((void**)&xk16, g_xk16);
    cudaGetSymbolAddress((void**)&xv16, g_xv16);
    cudaGetSymbolAddress((void**)&wq16, g_wq16);
    cudaGetSymbolAddress((void**)&wk16, g_wk16);
    cudaGetSymbolAddress((void**)&wv16, g_wv16);
    cudaGetSymbolAddress((void**)&q16, g_q16);
    cudaGetSymbolAddress((void**)&k16, g_k16);
    cudaGetSymbolAddress((void**)&v16, g_v16);
    cudaGetSymbolAddress((void**)&s16, g_s16);
    cudaGetSymbolAddress((void**)&p16, g_p16);
    cudaGetSymbolAddress((void**)&cp, g_ctx);
    cudaGetSymbolAddress((void**)&attn_scratch, g_attn);

    float* attn = ((long long)out_size >= BSD + BHSS) ? (out + BSD) : attn_scratch;

    const int CTX_SMEM = (2 * 128 * 72 + 2 * 64 * 72) * 2;   // 55296
    cudaFuncSetAttribute(ctx16_kernel, cudaFuncAttributeMaxDynamicSharedMemorySize, CTX_SMEM);

    const int M = Bc * Sc;  // 8192
    dim3 blk(256);

    // fp16 conversions
    cvt_f32_f16<<<dim3((int)(BSD / 4 / 256)), blk>>>(Q, xq16, (int)(BSD / 4));
    cvt_f32_f16<<<dim3((int)(BSD / 4 / 256)), blk>>>(K, xk16, (int)(BSD / 4));
    cvt_f32_f16<<<dim3((int)(BSD / 4 / 256)), blk>>>(V, xv16, (int)(BSD / 4));
    cvt_f32_f16<<<dim3(Dc * Dc / 4 / 256), blk>>>(wq, wq16, Dc * Dc / 4);
    cvt_f32_f16<<<dim3(Dc * Dc / 4 / 256), blk>>>(wk, wk16, Dc * Dc / 4);
    cvt_f32_f16<<<dim3(Dc * Dc / 4 / 256), blk>>>(wv, wv16, Dc * Dc / 4);

    // Projections (fp16 out)
    dim3 gProj(Dc / 128, M / 128);
    proj16_kernel<<<gProj, blk>>>(xq16, wq16, bq, q16, M, Dc, Dc);
    proj16_kernel<<<gProj, blk>>>(xk16, wk16, bk, k16, M, Dc, Dc);
    proj16_kernel<<<gProj, blk>>>(xv16, wv16, bv, v16, M, Dc, Dc);

    // Scores -> fp16
    dim3 gScore(Sc / 128, Sc / 128, Bc * Hc);
    scores16_kernel<<<gScore, blk>>>(s16, q16, k16);

    // Softmax: fp16 scores -> fp32 attn (final) + fp16 p
    softmax_kernel<<<dim3(Bc * Hc * Sc), blk>>>(s16, attn, p16);

    // Ctx (fp16 in, fp32 out)
    dim3 gCtx(Sc / 128, Bc * Hc);
    ctx16_kernel<<<gCtx, blk, CTX_SMEM>>>(p16, v16);

    // Output projection (tf32, fp32 out)
    proj_nt_kernel<<<gProj, blk>>>(cp, wo, out, bo, M, Dc, Dc);
}